// round 1
// baseline (speedup 1.0000x reference)
#include <cuda_runtime.h>
#include <cuda_bf16.h>
#include <math.h>
#include <stdint.h>

// Problem constants
#define NN   512
#define LL   64
#define DH   256
#define DX   64
#define QQ   8192
#define NTYP 16
#define NMEM 262144
#define NSEG (NN*LL)        // 32768

// Scratch (device globals; no allocation allowed)
__device__ float g_xsum[NSEG * DX];       // 8 MB
__device__ float g_qin [QQ * 2 * DH];     // 16 MB
__device__ float g_qp  [QQ * DH];         // 8 MB
__device__ float g_wv  [QQ * DH];         // 8 MB
__device__ int   g_em  [NN];
__device__ int   g_acc_cnt;

// ---------------------------------------------------------------------------
// Kernel 0: init scratch (must run every launch — deterministic)
// ---------------------------------------------------------------------------
__global__ void init_kernel() {
    int tid = blockIdx.x * blockDim.x + threadIdx.x;   // 2097152 threads
    g_xsum[tid] = 0.f;
    if (tid < NN) g_em[tid] = 0x7fffffff;
    if (tid == 0) g_acc_cnt = 0;
}

// ---------------------------------------------------------------------------
// Kernel 1: x_sum = segment_sum(tok_emb[mem], grp)
// one thread per (entry, channel): 262144*64 = 16.8M threads
// ---------------------------------------------------------------------------
__global__ void scatter_kernel(const float* __restrict__ tok_emb,
                               const int*   __restrict__ mem,
                               const int*   __restrict__ grp) {
    int tid = blockIdx.x * blockDim.x + threadIdx.x;
    int e = tid >> 6;
    int c = tid & 63;
    int tok = __ldg(&mem[e]);
    int g   = __ldg(&grp[e]);
    float v = __ldg(&tok_emb[(size_t)tok * DX + c]);
    atomicAdd(&g_xsum[(size_t)g * DX + c], v);
}

// ---------------------------------------------------------------------------
// Kernel 2: q_in[q] = cat(h_grp[idx[q], src[q]], h_grp[idx[q], dst[q]])
// one thread per element: 8192*512
// ---------------------------------------------------------------------------
__global__ void qin_kernel(const float* __restrict__ h_grp,
                           const int* __restrict__ idx,
                           const int* __restrict__ src,
                           const int* __restrict__ dst) {
    int tid = blockIdx.x * blockDim.x + threadIdx.x;
    int q = tid >> 9;
    int e = tid & 511;
    int i = __ldg(&idx[q]);
    int pos = (e < DH) ? __ldg(&src[q]) : __ldg(&dst[q]);
    g_qin[tid] = __ldg(&h_grp[((size_t)i * LL + pos) * DH + (e & (DH - 1))]);
}

// ---------------------------------------------------------------------------
// Tiled fp32 GEMM. C[m,n] = sum_k A[m,k] * B(..) + bias[n]
//   B_TRANS = true : B stored (N,K) row-major, B[n*K + k]
//   B_TRANS = false: B stored (K,N) row-major, B[k*N + n]
// BM=BN=64, BK=16, 256 threads, 4x4 per thread. Dims divide tiles evenly.
// ---------------------------------------------------------------------------
template <bool B_TRANS>
__global__ __launch_bounds__(256)
void gemm_kernel(const float* __restrict__ A, const float* __restrict__ B,
                 const float* __restrict__ bias, float* __restrict__ C,
                 int M, int N, int K) {
    const int BM = 64, BN = 64, BK = 16;
    __shared__ float As[BK][BM];
    __shared__ float Bs[BK][BN];
    int tid = threadIdx.x;
    int tx = tid & 15, ty = tid >> 4;
    int row0 = blockIdx.y * BM;
    int col0 = blockIdx.x * BN;

    float acc[4][4] = {};

    for (int k0 = 0; k0 < K; k0 += BK) {
        {   // A tile: float4 along K, scatter to As[k][m]
            int m  = tid >> 2;
            int k4 = (tid & 3) << 2;
            float4 v = *reinterpret_cast<const float4*>(&A[(size_t)(row0 + m) * K + k0 + k4]);
            As[k4 + 0][m] = v.x; As[k4 + 1][m] = v.y;
            As[k4 + 2][m] = v.z; As[k4 + 3][m] = v.w;
        }
        if (B_TRANS) {
            int n  = tid >> 2;
            int k4 = (tid & 3) << 2;
            float4 v = *reinterpret_cast<const float4*>(&B[(size_t)(col0 + n) * K + k0 + k4]);
            Bs[k4 + 0][n] = v.x; Bs[k4 + 1][n] = v.y;
            Bs[k4 + 2][n] = v.z; Bs[k4 + 3][n] = v.w;
        } else {
            int k  = tid >> 4;
            int n4 = (tid & 15) << 2;
            float4 v = *reinterpret_cast<const float4*>(&B[(size_t)(k0 + k) * N + col0 + n4]);
            *reinterpret_cast<float4*>(&Bs[k][n4]) = v;
        }
        __syncthreads();

        #pragma unroll
        for (int k = 0; k < BK; k++) {
            float4 a = *reinterpret_cast<const float4*>(&As[k][ty << 2]);
            float4 b = *reinterpret_cast<const float4*>(&Bs[k][tx << 2]);
            float av[4] = {a.x, a.y, a.z, a.w};
            float bv[4] = {b.x, b.y, b.z, b.w};
            #pragma unroll
            for (int i = 0; i < 4; i++)
                #pragma unroll
                for (int j = 0; j < 4; j++)
                    acc[i][j] += av[i] * bv[j];
        }
        __syncthreads();
    }

    #pragma unroll
    for (int i = 0; i < 4; i++) {
        int r = row0 + (ty << 2) + i;
        #pragma unroll
        for (int j = 0; j < 4; j++) {
            int c = col0 + (tx << 2) + j;
            float v = acc[i][j];
            if (bias) v += __ldg(&bias[c]);
            C[(size_t)r * N + c] = v;
        }
    }
}

// ---------------------------------------------------------------------------
// Kernel 5: per-query attention + rel head + metrics. One block per query.
// s[q,l] = (h_grp[i,l,:]·wv[q] + qp[q]·bk) / 16 ; softmax over l; attn;
// logit = cat(q_in, attn) @ Wrel^T + brel ; metrics via atomics.
// ---------------------------------------------------------------------------
__global__ __launch_bounds__(256)
void attn_kernel(const float* __restrict__ h_grp,
                 const float* __restrict__ Wrel,
                 const float* __restrict__ brel,
                 const float* __restrict__ bk,
                 const int*   __restrict__ idx,
                 const int*   __restrict__ pos2grp,
                 const int*   __restrict__ msk,
                 const int*   __restrict__ typ,
                 float* __restrict__ out_logit) {
    int q    = blockIdx.x;
    int tid  = threadIdx.x;     // 256
    int lane = tid & 31;
    int w    = tid >> 5;        // 8 warps

    __shared__ float s_wv[DH];
    __shared__ float s_s[LL];
    __shared__ float s_a[LL];
    __shared__ int   s_g[LL];
    __shared__ float s_attn[DX];
    __shared__ float s_part[256];
    __shared__ float s_red[8];
    __shared__ int   s_eq[NTYP];

    int i = __ldg(&idx[q]);

    s_wv[tid] = g_wv[(size_t)q * DH + tid];
    float cpart = g_qp[(size_t)q * DH + tid] * __ldg(&bk[tid]);
    #pragma unroll
    for (int o = 16; o > 0; o >>= 1) cpart += __shfl_xor_sync(0xffffffffu, cpart, o);
    if (lane == 0) s_red[w] = cpart;
    if (tid < LL) s_g[tid] = __ldg(&pos2grp[i * LL + tid]);
    __syncthreads();

    float c = 0.f;
    #pragma unroll
    for (int r = 0; r < 8; r++) c += s_red[r];

    // scores: warp w handles l = w*8 .. w*8+7
    const float* hbase = h_grp + (size_t)i * LL * DH;
    #pragma unroll
    for (int il = 0; il < 8; il++) {
        int l = (w << 3) + il;
        const float* hr = hbase + (size_t)l * DH;
        float p = 0.f;
        #pragma unroll
        for (int e = 0; e < DH; e += 32) p += __ldg(&hr[e + lane]) * s_wv[e + lane];
        #pragma unroll
        for (int o = 16; o > 0; o >>= 1) p += __shfl_xor_sync(0xffffffffu, p, o);
        if (lane == 0) {
            float sv = (p + c) * 0.0625f;           // / sqrt(256)
            if (__ldg(&msk[i * LL + l]) == 0) sv = -INFINITY;
            s_s[l] = sv;
        }
    }
    __syncthreads();

    // softmax over 64 by warp 0
    if (w == 0) {
        float v0 = s_s[lane], v1 = s_s[lane + 32];
        float m = fmaxf(v0, v1);
        #pragma unroll
        for (int o = 16; o > 0; o >>= 1) m = fmaxf(m, __shfl_xor_sync(0xffffffffu, m, o));
        float e0 = __expf(v0 - m), e1 = __expf(v1 - m);
        float ssum = e0 + e1;
        #pragma unroll
        for (int o = 16; o > 0; o >>= 1) ssum += __shfl_xor_sync(0xffffffffu, ssum, o);
        float inv = 1.f / ssum;
        s_a[lane] = e0 * inv; s_a[lane + 32] = e1 * inv;
    }
    __syncthreads();

    // attn[j] = sum_l a[l] * x_sum[g[l], j]
    {
        int j = tid & 63, part = tid >> 6;  // 4 parts x 16 l's
        float ap = 0.f;
        #pragma unroll
        for (int li = 0; li < 16; li++) {
            int l = (part << 4) + li;
            ap += s_a[l] * g_xsum[(size_t)s_g[l] * DX + j];
        }
        s_part[tid] = ap;
    }
    __syncthreads();
    if (tid < DX) s_attn[tid] = s_part[tid] + s_part[tid + 64] + s_part[tid + 128] + s_part[tid + 192];
    __syncthreads();

    // rel head: warp w computes t = 2w, 2w+1 ; dot length 576
    const float* qrow = g_qin + (size_t)q * (2 * DH);
    #pragma unroll
    for (int tt = 0; tt < 2; tt++) {
        int t = (w << 1) + tt;
        const float* wr = Wrel + (size_t)t * (2 * DH + DX);
        float p = 0.f;
        #pragma unroll
        for (int k = 0; k < 2 * DH; k += 32) p += qrow[k + lane] * __ldg(&wr[k + lane]);
        #pragma unroll
        for (int k = 0; k < DX; k += 32) p += s_attn[k + lane] * __ldg(&wr[2 * DH + k + lane]);
        #pragma unroll
        for (int o = 16; o > 0; o >>= 1) p += __shfl_xor_sync(0xffffffffu, p, o);
        if (lane == 0) {
            p += __ldg(&brel[t]);
            out_logit[(size_t)q * NTYP + t] = p;
            int gt = (p > 0.f) ? 1 : 0;
            int ty = (__ldg(&typ[q * NTYP + t]) > 0) ? 1 : 0;
            s_eq[t] = (gt == ty) ? 1 : 0;
        }
    }
    __syncthreads();
    if (tid == 0) {
        int cnt = 0, all = 1;
        #pragma unroll
        for (int t = 0; t < NTYP; t++) { cnt += s_eq[t]; all &= s_eq[t]; }
        atomicAdd(&g_acc_cnt, cnt);
        atomicMin(&g_em[i], all);
    }
}

// ---------------------------------------------------------------------------
// Kernel 6: finalize scalars. out layout: [logit(131072), acc, emr, em(512)]
// ---------------------------------------------------------------------------
__global__ __launch_bounds__(512)
void finalize_kernel(float* __restrict__ out) {
    __shared__ float s_red[16];
    int tid = threadIdx.x;            // 512
    int lane = tid & 31, w = tid >> 5;
    float e = (float)g_em[tid];
    out[QQ * NTYP + 2 + tid] = e;
    float p = e;
    #pragma unroll
    for (int o = 16; o > 0; o >>= 1) p += __shfl_xor_sync(0xffffffffu, p, o);
    if (lane == 0) s_red[w] = p;
    __syncthreads();
    if (tid == 0) {
        float sum = 0.f;
        #pragma unroll
        for (int r = 0; r < 16; r++) sum += s_red[r];
        out[QQ * NTYP + 0] = (float)g_acc_cnt / (float)(QQ * NTYP);
        out[QQ * NTYP + 1] = sum / (float)NN;
    }
}

// ---------------------------------------------------------------------------
extern "C" void kernel_launch(void* const* d_in, const int* in_sizes, int n_in,
                              void* d_out, int out_size) {
    const float* h_grp   = (const float*)d_in[0];
    const float* tok_emb = (const float*)d_in[1];
    const float* Wq      = (const float*)d_in[2];
    const float* bq      = (const float*)d_in[3];
    const float* Wk      = (const float*)d_in[4];
    const float* bk      = (const float*)d_in[5];
    const float* Wrel    = (const float*)d_in[6];
    const float* brel    = (const float*)d_in[7];
    const int*   mem     = (const int*)d_in[8];
    const int*   grp     = (const int*)d_in[9];
    const int*   pos2grp = (const int*)d_in[10];
    const int*   msk     = (const int*)d_in[11];
    const int*   idx     = (const int*)d_in[12];
    const int*   src     = (const int*)d_in[13];
    const int*   dst     = (const int*)d_in[14];
    const int*   typ     = (const int*)d_in[15];
    float* out = (float*)d_out;

    float* xsum_ptr; cudaGetSymbolAddress((void**)&xsum_ptr, g_xsum);
    float* qin_ptr;  cudaGetSymbolAddress((void**)&qin_ptr,  g_qin);
    float* qp_ptr;   cudaGetSymbolAddress((void**)&qp_ptr,   g_qp);
    float* wv_ptr;   cudaGetSymbolAddress((void**)&wv_ptr,   g_wv);

    // 0) init scratch: 32768*64 = 2,097,152 threads
    init_kernel<<<NSEG * DX / 256, 256>>>();

    // 1) segment-sum scatter: 262144*64 threads
    scatter_kernel<<<NMEM * 64 / 256, 256>>>(tok_emb, mem, grp);

    // 2) build q_in: 8192*512 threads
    qin_kernel<<<QQ * 2 * DH / 256, 256>>>(h_grp, idx, src, dst);

    // 3) qp = q_in @ Wq^T + bq   (M=8192, N=256, K=512, B row-major (N,K))
    {
        dim3 grid(DH / 64, QQ / 64);
        gemm_kernel<true><<<grid, 256>>>(qin_ptr, Wq, bq, qp_ptr, QQ, DH, 2 * DH);
    }
    // 4) wv = qp @ Wk            (M=8192, N=256, K=256, B row-major (K,N))
    {
        dim3 grid(DH / 64, QQ / 64);
        gemm_kernel<false><<<grid, 256>>>(qp_ptr, Wk, nullptr, wv_ptr, QQ, DH, DH);
    }
    // 5) attention + rel head + metrics
    attn_kernel<<<QQ, 256>>>(h_grp, Wrel, brel, bk, idx, pos2grp, msk, typ, out);

    // 6) finalize
    finalize_kernel<<<1, 512>>>(out);
}

// round 2
// speedup vs baseline: 1.2389x; 1.2389x over previous
#include <cuda_runtime.h>
#include <cuda_bf16.h>
#include <math.h>
#include <stdint.h>

// Problem constants
#define NN   512
#define LL   64
#define DH   256
#define DX   64
#define QQ   8192
#define NTYP 16
#define NMEM 262144
#define NSEG (NN*LL)        // 32768

// Scratch (device globals; no allocation allowed)
__device__ float g_xsum[NSEG * DX];       // 8 MB
__device__ float g_wv  [QQ * DH];         // 8 MB
__device__ float g_w2  [2 * DH * DH];     // 512x256 = WqT @ Wk
__device__ float g_u   [2 * DH];          // WqT @ bk
__device__ float g_b2  [DH];              // bq @ Wk
__device__ float g_cq;                    // bk . bq
__device__ int   g_em  [NN];
__device__ int   g_acc_cnt;

// ---------------------------------------------------------------------------
// Kernel 0: init scratch
// ---------------------------------------------------------------------------
__global__ void init_kernel() {
    int tid = blockIdx.x * blockDim.x + threadIdx.x;   // 2097152 threads
    g_xsum[tid] = 0.f;
    if (tid < NN) g_em[tid] = 0x7fffffff;
    if (tid == 0) g_acc_cnt = 0;
}

// ---------------------------------------------------------------------------
// Kernel 1: x_sum = segment_sum(tok_emb[mem], grp)
// ---------------------------------------------------------------------------
__global__ void scatter_kernel(const float* __restrict__ tok_emb,
                               const int*   __restrict__ mem,
                               const int*   __restrict__ grp) {
    int tid = blockIdx.x * blockDim.x + threadIdx.x;
    int e = tid >> 6;
    int c = tid & 63;
    int tok = __ldg(&mem[e]);
    int g   = __ldg(&grp[e]);
    float v = __ldg(&tok_emb[(size_t)tok * DX + c]);
    atomicAdd(&g_xsum[(size_t)g * DX + c], v);
}

// ---------------------------------------------------------------------------
// Kernel 2: W2[k,e] = sum_d Wq[d,k] * Wk[d,e]   (512 x 256, K=256)
// grid 32 blocks, each handles 16 k-rows x all 256 e. 256 threads.
// ---------------------------------------------------------------------------
__global__ __launch_bounds__(256)
void w2_kernel(const float* __restrict__ Wq, const float* __restrict__ Wk) {
    __shared__ float s_wq[DH][16];      // [d][kl]
    int tid = threadIdx.x;
    int k0 = blockIdx.x * 16;
    #pragma unroll
    for (int r = 0; r < 16; r++) {
        int fid = tid + r * 256;        // 0..4095
        int d = fid >> 4, kl = fid & 15;
        s_wq[d][kl] = __ldg(&Wq[(size_t)d * (2 * DH) + k0 + kl]);
    }
    __syncthreads();
    float acc[16] = {};
    int e = tid;
    #pragma unroll 4
    for (int d = 0; d < DH; d++) {
        float wkv = __ldg(&Wk[(size_t)d * DH + e]);
        #pragma unroll
        for (int kl = 0; kl < 16; kl++) acc[kl] += s_wq[d][kl] * wkv;
    }
    #pragma unroll
    for (int kl = 0; kl < 16; kl++)
        g_w2[(size_t)(k0 + kl) * DH + e] = acc[kl];
}

// ---------------------------------------------------------------------------
// Kernel 3: u[k] = sum_d bk[d]*Wq[d,k]; b2[e] = sum_d bq[d]*Wk[d,e]; cq = bk.bq
// one block, 512 threads
// ---------------------------------------------------------------------------
__global__ __launch_bounds__(512)
void vec_kernel(const float* __restrict__ Wq, const float* __restrict__ Wk,
                const float* __restrict__ bq, const float* __restrict__ bk) {
    int tid = threadIdx.x;
    float ua = 0.f;
    for (int d = 0; d < DH; d++) ua += __ldg(&bk[d]) * __ldg(&Wq[(size_t)d * (2 * DH) + tid]);
    g_u[tid] = ua;
    if (tid < DH) {
        float b2 = 0.f;
        for (int d = 0; d < DH; d++) b2 += __ldg(&bq[d]) * __ldg(&Wk[(size_t)d * DH + tid]);
        g_b2[tid] = b2;
    }
    if (tid == 0) {
        float c = 0.f;
        for (int d = 0; d < DH; d++) c += __ldg(&bk[d]) * __ldg(&bq[d]);
        g_cq = c;
    }
}

// ---------------------------------------------------------------------------
// Kernel 4: fused gather-GEMM: wv[q,e] = sum_k q_in[q,k]*W2[k,e] + b2[e]
//   q_in[q,k] = h_grp[idx[q], k<256 ? src[q] : dst[q], k&255]  (gathered)
// BM=BN=128, BK=16, 256 threads, 8x8 microtile, double-buffered.
// grid = (256/128, 8192/128) = (2, 64)
// ---------------------------------------------------------------------------
__global__ __launch_bounds__(256)
void gemm_fused(const float* __restrict__ h_grp,
                const int* __restrict__ idx,
                const int* __restrict__ src,
                const int* __restrict__ dst) {
    __shared__ float As[2][16][128];
    __shared__ float Bs[2][16][128];
    __shared__ int   sOff[2][128];

    const int tid  = threadIdx.x;
    const int row0 = blockIdx.y * 128;
    const int col0 = blockIdx.x * 128;

    if (tid < 128) {
        int q = row0 + tid;
        int i = __ldg(&idx[q]);
        sOff[0][tid] = (i * LL + __ldg(&src[q])) * DH;
        sOff[1][tid] = (i * LL + __ldg(&dst[q])) * DH;
    }
    __syncthreads();

    // A loader indices: fid = tid + j*256; m = fid>>2 (row), kc = (fid&3)*4
    const int am0 = tid >> 2,          akc0 = (tid & 3) * 4;
    const int am1 = (tid + 256) >> 2,  akc1 = (tid & 3) * 4;
    // B loader: fid = tid + j*256; k = fid>>5, c = (fid&31)*4
    const int bk0 = tid >> 5,          bc0 = (tid & 31) * 4;
    const int bk1 = (tid + 256) >> 5,  bc1 = (tid & 31) * 4;

    float4 rA0, rA1, rB0, rB1;

    auto loadTile = [&](int t) {
        int k0 = t * 16;
        int half = k0 >> 8;
        int kb = k0 & 255;
        rA0 = *reinterpret_cast<const float4*>(h_grp + sOff[half][am0] + kb + akc0);
        rA1 = *reinterpret_cast<const float4*>(h_grp + sOff[half][am1] + kb + akc1);
        rB0 = *reinterpret_cast<const float4*>(&g_w2[(size_t)(k0 + bk0) * DH + col0 + bc0]);
        rB1 = *reinterpret_cast<const float4*>(&g_w2[(size_t)(k0 + bk1) * DH + col0 + bc1]);
    };
    auto storeTile = [&](int buf) {
        As[buf][akc0 + 0][am0] = rA0.x; As[buf][akc0 + 1][am0] = rA0.y;
        As[buf][akc0 + 2][am0] = rA0.z; As[buf][akc0 + 3][am0] = rA0.w;
        As[buf][akc1 + 0][am1] = rA1.x; As[buf][akc1 + 1][am1] = rA1.y;
        As[buf][akc1 + 2][am1] = rA1.z; As[buf][akc1 + 3][am1] = rA1.w;
        *reinterpret_cast<float4*>(&Bs[buf][bk0][bc0]) = rB0;
        *reinterpret_cast<float4*>(&Bs[buf][bk1][bc1]) = rB1;
    };

    loadTile(0);
    storeTile(0);
    __syncthreads();

    float acc[8][8] = {};
    const int ty8 = (tid >> 4) * 8;
    const int tx8 = (tid & 15) * 8;

    for (int t = 0; t < 32; t++) {
        int buf = t & 1;
        if (t < 31) loadTile(t + 1);
        #pragma unroll
        for (int k = 0; k < 16; k++) {
            float4 a0 = *reinterpret_cast<const float4*>(&As[buf][k][ty8]);
            float4 a1 = *reinterpret_cast<const float4*>(&As[buf][k][ty8 + 4]);
            float4 b0 = *reinterpret_cast<const float4*>(&Bs[buf][k][tx8]);
            float4 b1 = *reinterpret_cast<const float4*>(&Bs[buf][k][tx8 + 4]);
            float av[8] = {a0.x, a0.y, a0.z, a0.w, a1.x, a1.y, a1.z, a1.w};
            float bv[8] = {b0.x, b0.y, b0.z, b0.w, b1.x, b1.y, b1.z, b1.w};
            #pragma unroll
            for (int i = 0; i < 8; i++)
                #pragma unroll
                for (int j = 0; j < 8; j++)
                    acc[i][j] += av[i] * bv[j];
        }
        if (t < 31) {
            storeTile(buf ^ 1);
            __syncthreads();
        }
    }

    float bb[8];
    #pragma unroll
    for (int j = 0; j < 8; j++) bb[j] = g_b2[col0 + tx8 + j];
    #pragma unroll
    for (int i = 0; i < 8; i++) {
        int q = row0 + ty8 + i;
        float* cr = g_wv + (size_t)q * DH + col0 + tx8;
        float4 o0 = {acc[i][0] + bb[0], acc[i][1] + bb[1], acc[i][2] + bb[2], acc[i][3] + bb[3]};
        float4 o1 = {acc[i][4] + bb[4], acc[i][5] + bb[5], acc[i][6] + bb[6], acc[i][7] + bb[7]};
        *reinterpret_cast<float4*>(cr)     = o0;
        *reinterpret_cast<float4*>(cr + 4) = o1;
    }
}

// ---------------------------------------------------------------------------
// Kernel 5: per-query attention + rel head + metrics. One block per query.
// ---------------------------------------------------------------------------
__global__ __launch_bounds__(256)
void attn_kernel(const float* __restrict__ h_grp,
                 const float* __restrict__ Wrel,
                 const float* __restrict__ brel,
                 const int*   __restrict__ idx,
                 const int*   __restrict__ src,
                 const int*   __restrict__ dst,
                 const int*   __restrict__ pos2grp,
                 const int*   __restrict__ msk,
                 const int*   __restrict__ typ,
                 float* __restrict__ out_logit) {
    int q    = blockIdx.x;
    int tid  = threadIdx.x;     // 256
    int lane = tid & 31;
    int w    = tid >> 5;        // 8 warps

    __shared__ float s_wv[DH];
    __shared__ float s_hq[2 * DH];   // gathered q_in row
    __shared__ float s_s[LL];
    __shared__ float s_a[LL];
    __shared__ int   s_g[LL];
    __shared__ float s_attn[DX];
    __shared__ float s_part[256];
    __shared__ float s_red[8];
    __shared__ int   s_eq[NTYP];

    int i = __ldg(&idx[q]);
    int sp = __ldg(&src[q]);
    int dp = __ldg(&dst[q]);

    const float* hs = h_grp + ((size_t)i * LL + sp) * DH;
    const float* hd = h_grp + ((size_t)i * LL + dp) * DH;
    float v1 = __ldg(&hs[tid]);
    float v2 = __ldg(&hd[tid]);
    s_hq[tid]       = v1;
    s_hq[tid + DH]  = v2;
    s_wv[tid] = g_wv[(size_t)q * DH + tid];

    // c = q_in . u + cq
    float cpart = v1 * g_u[tid] + v2 * g_u[tid + DH];
    #pragma unroll
    for (int o = 16; o > 0; o >>= 1) cpart += __shfl_xor_sync(0xffffffffu, cpart, o);
    if (lane == 0) s_red[w] = cpart;
    if (tid < LL) s_g[tid] = __ldg(&pos2grp[i * LL + tid]);
    __syncthreads();

    float c = g_cq;
    #pragma unroll
    for (int r = 0; r < 8; r++) c += s_red[r];

    // scores: warp w handles l = w*8 .. w*8+7
    const float* hbase = h_grp + (size_t)i * LL * DH;
    #pragma unroll
    for (int il = 0; il < 8; il++) {
        int l = (w << 3) + il;
        const float* hr = hbase + (size_t)l * DH;
        float p = 0.f;
        #pragma unroll
        for (int e = 0; e < DH; e += 32) p += __ldg(&hr[e + lane]) * s_wv[e + lane];
        #pragma unroll
        for (int o = 16; o > 0; o >>= 1) p += __shfl_xor_sync(0xffffffffu, p, o);
        if (lane == 0) {
            float sv = (p + c) * 0.0625f;           // / sqrt(256)
            if (__ldg(&msk[i * LL + l]) == 0) sv = -INFINITY;
            s_s[l] = sv;
        }
    }
    __syncthreads();

    // softmax over 64 by warp 0
    if (w == 0) {
        float v0 = s_s[lane], vv1 = s_s[lane + 32];
        float m = fmaxf(v0, vv1);
        #pragma unroll
        for (int o = 16; o > 0; o >>= 1) m = fmaxf(m, __shfl_xor_sync(0xffffffffu, m, o));
        float e0 = __expf(v0 - m), e1 = __expf(vv1 - m);
        float ssum = e0 + e1;
        #pragma unroll
        for (int o = 16; o > 0; o >>= 1) ssum += __shfl_xor_sync(0xffffffffu, ssum, o);
        float inv = 1.f / ssum;
        s_a[lane] = e0 * inv; s_a[lane + 32] = e1 * inv;
    }
    __syncthreads();

    // attn[j] = sum_l a[l] * x_sum[g[l], j]
    {
        int j = tid & 63, part = tid >> 6;  // 4 parts x 16 l's
        float ap = 0.f;
        #pragma unroll
        for (int li = 0; li < 16; li++) {
            int l = (part << 4) + li;
            ap += s_a[l] * g_xsum[(size_t)s_g[l] * DX + j];
        }
        s_part[tid] = ap;
    }
    __syncthreads();
    if (tid < DX) s_attn[tid] = s_part[tid] + s_part[tid + 64] + s_part[tid + 128] + s_part[tid + 192];
    __syncthreads();

    // rel head: warp w computes t = 2w, 2w+1 ; dot length 576
    #pragma unroll
    for (int tt = 0; tt < 2; tt++) {
        int t = (w << 1) + tt;
        const float* wr = Wrel + (size_t)t * (2 * DH + DX);
        float p = 0.f;
        #pragma unroll
        for (int k = 0; k < 2 * DH; k += 32) p += s_hq[k + lane] * __ldg(&wr[k + lane]);
        #pragma unroll
        for (int k = 0; k < DX; k += 32) p += s_attn[k + lane] * __ldg(&wr[2 * DH + k + lane]);
        #pragma unroll
        for (int o = 16; o > 0; o >>= 1) p += __shfl_xor_sync(0xffffffffu, p, o);
        if (lane == 0) {
            p += __ldg(&brel[t]);
            out_logit[(size_t)q * NTYP + t] = p;
            int gt = (p > 0.f) ? 1 : 0;
            int ty = (__ldg(&typ[q * NTYP + t]) > 0) ? 1 : 0;
            s_eq[t] = (gt == ty) ? 1 : 0;
        }
    }
    __syncthreads();
    if (tid == 0) {
        int cnt = 0, all = 1;
        #pragma unroll
        for (int t = 0; t < NTYP; t++) { cnt += s_eq[t]; all &= s_eq[t]; }
        atomicAdd(&g_acc_cnt, cnt);
        atomicMin(&g_em[i], all);
    }
}

// ---------------------------------------------------------------------------
// Kernel 6: finalize scalars. out layout: [logit(131072), acc, emr, em(512)]
// ---------------------------------------------------------------------------
__global__ __launch_bounds__(512)
void finalize_kernel(float* __restrict__ out) {
    __shared__ float s_red[16];
    int tid = threadIdx.x;            // 512
    int lane = tid & 31, w = tid >> 5;
    float e = (float)g_em[tid];
    out[QQ * NTYP + 2 + tid] = e;
    float p = e;
    #pragma unroll
    for (int o = 16; o > 0; o >>= 1) p += __shfl_xor_sync(0xffffffffu, p, o);
    if (lane == 0) s_red[w] = p;
    __syncthreads();
    if (tid == 0) {
        float sum = 0.f;
        #pragma unroll
        for (int r = 0; r < 16; r++) sum += s_red[r];
        out[QQ * NTYP + 0] = (float)g_acc_cnt / (float)(QQ * NTYP);
        out[QQ * NTYP + 1] = sum / (float)NN;
    }
}

// ---------------------------------------------------------------------------
extern "C" void kernel_launch(void* const* d_in, const int* in_sizes, int n_in,
                              void* d_out, int out_size) {
    const float* h_grp   = (const float*)d_in[0];
    const float* tok_emb = (const float*)d_in[1];
    const float* Wq      = (const float*)d_in[2];
    const float* bq      = (const float*)d_in[3];
    const float* Wk      = (const float*)d_in[4];
    const float* bk      = (const float*)d_in[5];
    const float* Wrel    = (const float*)d_in[6];
    const float* brel    = (const float*)d_in[7];
    const int*   mem     = (const int*)d_in[8];
    const int*   grp     = (const int*)d_in[9];
    const int*   pos2grp = (const int*)d_in[10];
    const int*   msk     = (const int*)d_in[11];
    const int*   idx     = (const int*)d_in[12];
    const int*   src     = (const int*)d_in[13];
    const int*   dst     = (const int*)d_in[14];
    const int*   typ     = (const int*)d_in[15];
    float* out = (float*)d_out;

    // 0) init scratch
    init_kernel<<<NSEG * DX / 256, 256>>>();

    // 2,3) tiny precompute (independent of scatter)
    w2_kernel<<<32, 256>>>(Wq, Wk);
    vec_kernel<<<1, 512>>>(Wq, Wk, bq, bk);

    // 1) segment-sum scatter
    scatter_kernel<<<NMEM * 64 / 256, 256>>>(tok_emb, mem, grp);

    // 4) fused gather-GEMM: wv
    {
        dim3 grid(DH / 128, QQ / 128);
        gemm_fused<<<grid, 256>>>(h_grp, idx, src, dst);
    }

    // 5) attention + rel head + metrics
    attn_kernel<<<QQ, 256>>>(h_grp, Wrel, brel, idx, src, dst, pos2grp, msk, typ, out);

    // 6) finalize
    finalize_kernel<<<1, 512>>>(out);
}